// round 1
// baseline (speedup 1.0000x reference)
#include <cuda_runtime.h>

// Problem constants: M=5, N=2 -> U=3, GROUPS=4, DIL=2, KSIZE=13
// x: (8, 256, 16384) f32 ; w: (256, 64, 13) f32 ; b: (256,) f32 ; out: (8, 256, 16384) f32
#define TI 8192        // per-phase length
#define TFULL 16384
#define OCH 256
#define BOUND 1.41421356237309515f

// Packed weights: per (o, c): [wc0..wc4, wa0..wa4, wb0..wb4]
//  wc[j] = w[3j]                      (C / t0 filter, 5 taps)
//  wa = diff filter for A[s+1]-A[s]:  [-w2, w2-w5, w5-w8, w8-w11, w11]
//  wb = diff filter for B[s+1]-B[s]:  [-w1, w1-w4, w4-w7, w7-w10, w10]
__device__ float g_wpack[256 * 64 * 15];

__global__ void pack_w_kernel(const float* __restrict__ w) {
    int o = blockIdx.x;     // 0..255
    int c = threadIdx.x;    // 0..63
    const float* ws = w + ((size_t)o * 64 + c) * 13;
    float* d = g_wpack + ((size_t)o * 64 + c) * 15;
    d[0]  = ws[0];  d[1] = ws[3];  d[2] = ws[6];  d[3] = ws[9];  d[4] = ws[12];
    d[5]  = -ws[2]; d[6] = ws[2] - ws[5];  d[7] = ws[5] - ws[8];
    d[8]  = ws[8] - ws[11];               d[9] = ws[11];
    d[10] = -ws[1]; d[11] = ws[1] - ws[4]; d[12] = ws[4] - ws[7];
    d[13] = ws[7] - ws[10];               d[14] = ws[10];
}

// Grid: (128 t-tiles, 8 batches * 2 phases, 4 groups). Block: 256 threads.
// Thread -> (o = tid>>2 in [0,64), trun = tid&3). Each thread: 16 contiguous t,
// with a +-2 halo on the C accumulator for the denom window (thread-local).
__global__ __launch_bounds__(256, 2) void pconv_kernel(
    const float* __restrict__ x,
    const float* __restrict__ bias,
    float* __restrict__ out)
{
    __shared__ float sx[64][72];   // xs[c][ttile-4 .. ttile+68)

    const int ttile = blockIdx.x * 64;
    const int batch = blockIdx.y >> 1;
    const int phase = blockIdx.y & 1;
    const int g     = blockIdx.z;

    // Stage x tile: xs[c][p] = x[batch][g*64+c][2p + phase], clamp to 0 outside [0, TI)
    const float* xb = x + ((size_t)batch * OCH + (size_t)g * 64) * TFULL + phase;
    for (int idx = threadIdx.x; idx < 64 * 72; idx += 256) {
        int c = idx / 72;
        int m = idx - c * 72;
        int p = ttile - 4 + m;
        sx[c][m] = (p >= 0 && p < TI) ? xb[(size_t)c * TFULL + 2 * p] : 0.f;
    }
    __syncthreads();

    const int o    = threadIdx.x >> 2;   // output channel within group
    const int trun = threadIdx.x & 3;
    const int tb   = ttile + trun * 16;  // thread's base output position t
    const int sb   = trun * 16;          // offset into sx row (cpos = tb-4+q -> sx[sb+q])

    float Cc[20], dA[16], dB[16];
    #pragma unroll
    for (int q = 0; q < 20; q++) Cc[q] = 0.f;
    #pragma unroll
    for (int p = 0; p < 16; p++) { dA[p] = 0.f; dB[p] = 0.f; }

    const float* wpo = g_wpack + ((size_t)(g * 64 + o) * 64) * 15;

    for (int c = 0; c < 64; ++c) {
        const float* w = wpo + c * 15;
        float wc0 = w[0],  wc1 = w[1],  wc2 = w[2],  wc3 = w[3],  wc4 = w[4];
        float wa0 = w[5],  wa1 = w[6],  wa2 = w[7],  wa3 = w[8],  wa4 = w[9];
        float wb0 = w[10], wb1 = w[11], wb2 = w[12], wb3 = w[13], wb4 = w[14];

        const float* xr = &sx[c][sb];
        float xv[24];
        #pragma unroll
        for (int m = 0; m < 24; m++) xv[m] = xr[m];

        #pragma unroll
        for (int q = 0; q < 20; q++)
            Cc[q] += xv[q] * wc0 + xv[q+1] * wc1 + xv[q+2] * wc2
                   + xv[q+3] * wc3 + xv[q+4] * wc4;

        #pragma unroll
        for (int p = 0; p < 16; p++) {
            dA[p] += xv[p+2] * wa0 + xv[p+3] * wa1 + xv[p+4] * wa2
                   + xv[p+5] * wa3 + xv[p+6] * wa4;
            dB[p] += xv[p+2] * wb0 + xv[p+3] * wb1 + xv[p+4] * wb2
                   + xv[p+5] * wb3 + xv[p+6] * wb4;
        }
    }

    const float bv = bias[g * 64 + o];
    float* outp = out + ((size_t)batch * OCH + (size_t)g * 64 + o) * TFULL + phase;

    #pragma unroll
    for (int p = 0; p < 16; p++) {
        int t = tb + p;
        // t0 window (values zero outside valid range [2, 8190))
        int t0 = t - 2, t1 = t - 1, t3 = t + 1, t4 = t + 2;
        float s0 = (t0 >= 2 && t0 < TI - 2) ? Cc[p + 0] + bv : 0.f;
        float s1 = (t1 >= 2 && t1 < TI - 2) ? Cc[p + 1] + bv : 0.f;
        float s2 = (t  >= 2 && t  < TI - 2) ? Cc[p + 2] + bv : 0.f;
        float s3 = (t3 >= 2 && t3 < TI - 2) ? Cc[p + 3] + bv : 0.f;
        float s4 = (t4 >= 2 && t4 < TI - 2) ? Cc[p + 4] + bv : 0.f;

        float mean = (s0 + s1 + s2 + s3 + s4) * 0.2f;
        float den  = fminf(fmaxf(s2 - mean, 1.0f), BOUND);
        float inv  = 1.0f / den;

        bool valid = (t >= 2 && t < TI - 2);
        float d1 = valid ? dA[p] : 0.f;
        float d2 = valid ? dB[p] : 0.f;

        float dia = 0.25f * (s2 + (d1 + d2) * inv + 2.f * (d2 - d1) * inv * inv);
        outp[2 * t] = dia;
    }
}

extern "C" void kernel_launch(void* const* d_in, const int* in_sizes, int n_in,
                              void* d_out, int out_size)
{
    const float* x = (const float*)d_in[0];
    const float* w = (const float*)d_in[1];
    const float* b = (const float*)d_in[2];
    float* out = (float*)d_out;

    pack_w_kernel<<<256, 64>>>(w);

    dim3 grid(TI / 64, 8 * 2, 4);
    pconv_kernel<<<grid, 256>>>(x, b, out);
}

// round 2
// speedup vs baseline: 1.0019x; 1.0019x over previous
#include <cuda_runtime.h>

// Problem constants: M=5, N=2 -> U=3, GROUPS=4, DIL=2, KSIZE=13
// x: (8, 256, 16384) f32 ; w: (256, 64, 13) f32 ; b: (256,) f32 ; out: (8, 256, 16384) f32
#define TI 8192        // per-phase length
#define TFULL 16384
#define OCH 256
#define BOUND 1.41421356237309515f

// Packed weights: per (o, c): [wc0..wc4, wa0..wa4, wb0..wb4]
//  wc[j] = w[3j]                      (C / t0 filter, 5 taps)
//  wa = diff filter for A[s+1]-A[s]:  [-w2, w2-w5, w5-w8, w8-w11, w11]
//  wb = diff filter for B[s+1]-B[s]:  [-w1, w1-w4, w4-w7, w7-w10, w10]
__device__ float g_wpack[256 * 64 * 15];

__global__ void pack_w_kernel(const float* __restrict__ w) {
    int o = blockIdx.x;     // 0..255
    int c = threadIdx.x;    // 0..63
    const float* ws = w + ((size_t)o * 64 + c) * 13;
    float* d = g_wpack + ((size_t)o * 64 + c) * 15;
    d[0]  = ws[0];  d[1] = ws[3];  d[2] = ws[6];  d[3] = ws[9];  d[4] = ws[12];
    d[5]  = -ws[2]; d[6] = ws[2] - ws[5];  d[7] = ws[5] - ws[8];
    d[8]  = ws[8] - ws[11];               d[9] = ws[11];
    d[10] = -ws[1]; d[11] = ws[1] - ws[4]; d[12] = ws[4] - ws[7];
    d[13] = ws[7] - ws[10];               d[14] = ws[10];
}

// Grid: (128 t-tiles, 8 batches * 2 phases, 4 groups). Block: 256 threads.
// Thread -> (o = tid>>2 in [0,64), trun = tid&3). Each thread: 16 contiguous t,
// with a +-2 halo on the C accumulator for the denom window (thread-local).
__global__ __launch_bounds__(256, 2) void pconv_kernel(
    const float* __restrict__ x,
    const float* __restrict__ bias,
    float* __restrict__ out)
{
    __shared__ float sx[64][72];   // xs[c][ttile-4 .. ttile+68)

    const int ttile = blockIdx.x * 64;
    const int batch = blockIdx.y >> 1;
    const int phase = blockIdx.y & 1;
    const int g     = blockIdx.z;

    // Stage x tile: xs[c][p] = x[batch][g*64+c][2p + phase], clamp to 0 outside [0, TI)
    const float* xb = x + ((size_t)batch * OCH + (size_t)g * 64) * TFULL + phase;
    for (int idx = threadIdx.x; idx < 64 * 72; idx += 256) {
        int c = idx / 72;
        int m = idx - c * 72;
        int p = ttile - 4 + m;
        sx[c][m] = (p >= 0 && p < TI) ? xb[(size_t)c * TFULL + 2 * p] : 0.f;
    }
    __syncthreads();

    const int o    = threadIdx.x >> 2;   // output channel within group
    const int trun = threadIdx.x & 3;
    const int tb   = ttile + trun * 16;  // thread's base output position t
    const int sb   = trun * 16;          // offset into sx row (cpos = tb-4+q -> sx[sb+q])

    float Cc[20], dA[16], dB[16];
    #pragma unroll
    for (int q = 0; q < 20; q++) Cc[q] = 0.f;
    #pragma unroll
    for (int p = 0; p < 16; p++) { dA[p] = 0.f; dB[p] = 0.f; }

    const float* wpo = g_wpack + ((size_t)(g * 64 + o) * 64) * 15;

    for (int c = 0; c < 64; ++c) {
        const float* w = wpo + c * 15;
        float wc0 = w[0],  wc1 = w[1],  wc2 = w[2],  wc3 = w[3],  wc4 = w[4];
        float wa0 = w[5],  wa1 = w[6],  wa2 = w[7],  wa3 = w[8],  wa4 = w[9];
        float wb0 = w[10], wb1 = w[11], wb2 = w[12], wb3 = w[13], wb4 = w[14];

        const float* xr = &sx[c][sb];
        float xv[24];
        #pragma unroll
        for (int m = 0; m < 24; m++) xv[m] = xr[m];

        #pragma unroll
        for (int q = 0; q < 20; q++)
            Cc[q] += xv[q] * wc0 + xv[q+1] * wc1 + xv[q+2] * wc2
                   + xv[q+3] * wc3 + xv[q+4] * wc4;

        #pragma unroll
        for (int p = 0; p < 16; p++) {
            dA[p] += xv[p+2] * wa0 + xv[p+3] * wa1 + xv[p+4] * wa2
                   + xv[p+5] * wa3 + xv[p+6] * wa4;
            dB[p] += xv[p+2] * wb0 + xv[p+3] * wb1 + xv[p+4] * wb2
                   + xv[p+5] * wb3 + xv[p+6] * wb4;
        }
    }

    const float bv = bias[g * 64 + o];
    float* outp = out + ((size_t)batch * OCH + (size_t)g * 64 + o) * TFULL + phase;

    #pragma unroll
    for (int p = 0; p < 16; p++) {
        int t = tb + p;
        // t0 window (values zero outside valid range [2, 8190))
        int t0 = t - 2, t1 = t - 1, t3 = t + 1, t4 = t + 2;
        float s0 = (t0 >= 2 && t0 < TI - 2) ? Cc[p + 0] + bv : 0.f;
        float s1 = (t1 >= 2 && t1 < TI - 2) ? Cc[p + 1] + bv : 0.f;
        float s2 = (t  >= 2 && t  < TI - 2) ? Cc[p + 2] + bv : 0.f;
        float s3 = (t3 >= 2 && t3 < TI - 2) ? Cc[p + 3] + bv : 0.f;
        float s4 = (t4 >= 2 && t4 < TI - 2) ? Cc[p + 4] + bv : 0.f;

        float mean = (s0 + s1 + s2 + s3 + s4) * 0.2f;
        float den  = fminf(fmaxf(s2 - mean, 1.0f), BOUND);
        float inv  = 1.0f / den;

        bool valid = (t >= 2 && t < TI - 2);
        float d1 = valid ? dA[p] : 0.f;
        float d2 = valid ? dB[p] : 0.f;

        float dia = 0.25f * (s2 + (d1 + d2) * inv + 2.f * (d2 - d1) * inv * inv);
        outp[2 * t] = dia;
    }
}

extern "C" void kernel_launch(void* const* d_in, const int* in_sizes, int n_in,
                              void* d_out, int out_size)
{
    const float* x = (const float*)d_in[0];
    const float* w = (const float*)d_in[1];
    const float* b = (const float*)d_in[2];
    float* out = (float*)d_out;

    pack_w_kernel<<<256, 64>>>(w);

    dim3 grid(TI / 64, 8 * 2, 4);
    pconv_kernel<<<grid, 256>>>(x, b, out);
}

// round 4
// speedup vs baseline: 2.6303x; 2.6253x over previous
#include <cuda_runtime.h>
#include <cuda_bf16.h>
#include <cstdint>

// x:(8,256,16384) f32, w:(256,64,13) f32, b:(256) f32 -> out:(8,256,16384) f32
// M=5,N=2 -> U=3, GROUPS=4, DIL=2
#define TI      8192
#define TFULL   16384
#define TSTRIDE 124
#define NT      67
#define XR      132
#define XPW     40                 // x row pitch (words)
#define BPW     40                 // B row pitch (words)
#define BROWS   192
#define BCHUNK  (BROWS * BPW * 4)  // 30720 B per hi or lo block
#define BCH16   (BCHUNK / 16)
#define EPITCH  194
#define BOUND   1.41421356237309515f

// smem layout (bytes)
#define XH_OFF   0
#define XL_OFF   (XR * XPW * 4)        // 21120
#define BH_OFF   (2 * XR * XPW * 4)    // 42240
#define BL_OFF   (BH_OFF + BCHUNK)     // 72960
#define SMEMSZ   (BL_OFF + BCHUNK)     // 103680  (epilogue 128x194 f32 = 99328 overlays)

// Pre-swizzled packed weights: [g][tap][hi/lo] blocks of 192 rows x 40 words
__device__ uint4 g_wB[4 * 5 * 2 * BCH16];

__device__ __forceinline__ int swz(int r) { return (r & 3) ^ ((r >> 2) & 3); }

__device__ __forceinline__ uint32_t smem_u32(const void* p) {
    uint32_t a;
    asm("{ .reg .u64 t; cvta.to.shared.u64 t, %1; cvt.u32.u64 %0, t; }" : "=r"(a) : "l"(p));
    return a;
}
__device__ __forceinline__ uint2 lds64(uint32_t addr) {
    uint2 v;
    asm volatile("ld.shared.v2.b32 {%0,%1}, [%2];" : "=r"(v.x), "=r"(v.y) : "r"(addr));
    return v;
}
__device__ __forceinline__ void mma16816(float* c, uint32_t a0, uint32_t a1,
                                         uint32_t a2, uint32_t a3,
                                         uint32_t b0, uint32_t b1) {
    asm volatile(
        "mma.sync.aligned.m16n8k16.row.col.f32.bf16.bf16.f32 "
        "{%0,%1,%2,%3}, {%4,%5,%6,%7}, {%8,%9}, {%0,%1,%2,%3};"
        : "+f"(c[0]), "+f"(c[1]), "+f"(c[2]), "+f"(c[3])
        : "r"(a0), "r"(a1), "r"(a2), "r"(a3), "r"(b0), "r"(b1));
}

// ---------------- weight prep: fused filters, bf16 hi/lo, swizzled image ----------------
// Fused filters (bias cancels in d1/d2):
//  t0:  wc[j] = w[3j]
//  d1:  [-w2, w2-w5, w5-w8, w8-w11, w11]
//  d2:  [-w1, w1-w4, w4-w7, w7-w10, w10]
__global__ void pack_w(const float* __restrict__ w) {
    int o = blockIdx.x;      // 0..255
    int c = threadIdx.x;     // 0..63
    int g = o >> 6, oo = o & 63;
    const float* ws = w + ((size_t)o * 64 + c) * 13;
    float f[3][5];
    #pragma unroll
    for (int j = 0; j < 5; j++) f[0][j] = ws[3 * j];
    f[1][0] = -ws[2];  f[1][1] = ws[2] - ws[5];  f[1][2] = ws[5] - ws[8];
    f[1][3] = ws[8] - ws[11];  f[1][4] = ws[11];
    f[2][0] = -ws[1];  f[2][1] = ws[1] - ws[4];  f[2][2] = ws[4] - ws[7];
    f[2][3] = ws[7] - ws[10];  f[2][4] = ws[10];

    int wl  = c >> 1;                 // logical k-word
    int q   = wl & 3, hi = (wl >> 2) & 1, cblk = wl >> 3;
    int sub = c & 1;
    char* base = (char*)g_wB;
    #pragma unroll
    for (int fi = 0; fi < 3; fi++) {
        int n = fi * 64 + oo;
        int pw = cblk * 8 + 2 * (q ^ swz(n)) + hi;
        size_t rowoff = (size_t)n * BPW * 4 + (size_t)pw * 4 + sub * 2;
        #pragma unroll
        for (int j = 0; j < 5; j++) {
            float v = f[fi][j];
            __nv_bfloat16 vh = __float2bfloat16(v);
            __nv_bfloat16 vl = __float2bfloat16(v - __bfloat162float(vh));
            size_t bh = ((size_t)(g * 5 + j) * 2 + 0) * BCHUNK;
            size_t bl = ((size_t)(g * 5 + j) * 2 + 1) * BCHUNK;
            *(__nv_bfloat16*)(base + bh + rowoff) = vh;
            *(__nv_bfloat16*)(base + bl + rowoff) = vl;
        }
    }
}

// ---------------- main kernel ----------------
// grid (67, 16, 4), 256 threads. Warp (wm = wid&3, wn = wid>>2): M rows wm*32..+31,
// N cols wn*96..+95. Tile row m <-> t = tbase + m - 2; A[m, (j,c)] = xs[tbase + m - 4 + j][c].
__global__ void __launch_bounds__(256, 1) pconv_mma(
    const float* __restrict__ x, const float* __restrict__ bias, float* __restrict__ out)
{
    extern __shared__ char smem[];
    const uint32_t sb = smem_u32(smem);
    const int tid = threadIdx.x, lane = tid & 31, wid = tid >> 5;
    const int wm = wid & 3, wn = wid >> 2;
    const int q = lane & 3, ls = lane >> 2;
    const int tbase = blockIdx.x * TSTRIDE;
    const int batch = blockIdx.y >> 1, phase = blockIdx.y & 1;
    const int g = blockIdx.z;

    // ---- stage x tile: rows p = tbase-4+m, bf16 hi/lo, swizzled pair layout ----
    {
        uint32_t* xhw = (uint32_t*)(smem + XH_OFF);
        uint32_t* xlw = (uint32_t*)(smem + XL_OFF);
        const float* xg = x + ((size_t)batch * 256 + (size_t)g * 64) * TFULL + phase;
        for (int idx = tid; idx < 32 * XR; idx += 256) {
            int i = idx / XR;            // channel pair 0..31
            int m = idx - i * XR;        // row 0..131
            int p = tbase - 4 + m;
            float v0 = 0.f, v1 = 0.f;
            if (p >= 0 && p < TI) {
                v0 = xg[(size_t)(2 * i) * TFULL + 2 * (size_t)p];
                v1 = xg[(size_t)(2 * i + 1) * TFULL + 2 * (size_t)p];
            }
            __nv_bfloat16 h0 = __float2bfloat16(v0);
            __nv_bfloat16 l0 = __float2bfloat16(v0 - __bfloat162float(h0));
            __nv_bfloat16 h1 = __float2bfloat16(v1);
            __nv_bfloat16 l1 = __float2bfloat16(v1 - __bfloat162float(h1));
            int iq = i & 3, ih = (i >> 2) & 1, icb = i >> 3;
            int pw = icb * 8 + 2 * (iq ^ swz(m)) + ih;
            int off = m * XPW + pw;
            xhw[off] = (uint32_t)__bfloat16_as_ushort(h0) | ((uint32_t)__bfloat16_as_ushort(h1) << 16);
            xlw[off] = (uint32_t)__bfloat16_as_ushort(l0) | ((uint32_t)__bfloat16_as_ushort(l1) << 16);
        }
    }

    float acc[2][12][4];
    #pragma unroll
    for (int mi = 0; mi < 2; mi++)
        #pragma unroll
        for (int ni = 0; ni < 12; ni++)
            #pragma unroll
            for (int k = 0; k < 4; k++) acc[mi][ni][k] = 0.f;

    const uint4* wB = g_wB + (size_t)g * 5 * 2 * BCH16;
    uint4* bsm = (uint4*)(smem + BH_OFF);

    for (int j = 0; j < 5; j++) {
        __syncthreads();   // previous tap's B reads done
        const uint4* src = wB + (size_t)j * 2 * BCH16;
        for (int idx = tid; idx < 2 * BCH16; idx += 256) bsm[idx] = src[idx];
        __syncthreads();

        #pragma unroll
        for (int cblk = 0; cblk < 4; cblk++) {
            // A fragments (hi/lo), rows r and r+8 per m-subtile
            uint2 ah[2][2], al[2][2];
            #pragma unroll
            for (int mi = 0; mi < 2; mi++) {
                int r0 = wm * 32 + mi * 16 + ls + j;
                #pragma unroll
                for (int ro = 0; ro < 2; ro++) {
                    int r = r0 + ro * 8;
                    uint32_t woff = (uint32_t)(r * XPW + cblk * 8 + 2 * (q ^ swz(r))) * 4;
                    ah[mi][ro] = lds64(sb + XH_OFF + woff);
                    al[mi][ro] = lds64(sb + XL_OFF + woff);
                }
            }
            #pragma unroll
            for (int ni = 0; ni < 12; ni++) {
                int n = wn * 96 + ni * 8 + ls;
                uint32_t woff = (uint32_t)(n * BPW + cblk * 8 + 2 * (q ^ swz(n))) * 4;
                uint2 bh = lds64(sb + BH_OFF + woff);
                uint2 bl = lds64(sb + BL_OFF + woff);
                #pragma unroll
                for (int mi = 0; mi < 2; mi++) {
                    mma16816(acc[mi][ni], ah[mi][0].x, ah[mi][1].x, ah[mi][0].y, ah[mi][1].y, bh.x, bh.y);
                    mma16816(acc[mi][ni], al[mi][0].x, al[mi][1].x, al[mi][0].y, al[mi][1].y, bh.x, bh.y);
                    mma16816(acc[mi][ni], ah[mi][0].x, ah[mi][1].x, ah[mi][0].y, ah[mi][1].y, bl.x, bl.y);
                }
            }
        }
    }

    // ---- epilogue: dump acc -> smem [128][194] f32 (overlays stage buffers) ----
    __syncthreads();
    float* eb = (float*)smem;
    #pragma unroll
    for (int mi = 0; mi < 2; mi++) {
        int r0 = wm * 32 + mi * 16 + ls;
        #pragma unroll
        for (int ni = 0; ni < 12; ni++) {
            int col = wn * 96 + ni * 8 + q * 2;
            *(float2*)&eb[r0 * EPITCH + col]       = make_float2(acc[mi][ni][0], acc[mi][ni][1]);
            *(float2*)&eb[(r0 + 8) * EPITCH + col] = make_float2(acc[mi][ni][2], acc[mi][ni][3]);
        }
    }
    __syncthreads();

    // outputs: rows m = 2..125 (t = tbase + m - 2), 64 channels
    #pragma unroll 1
    for (int ko = 0; ko < 8; ko++) {
        int o = wid * 8 + ko;
        float bv = __ldg(&bias[g * 64 + o]);
        float* op = out + ((size_t)batch * 256 + (size_t)g * 64 + o) * TFULL + phase;
        #pragma unroll 1
        for (int rb = 0; rb < 4; rb++) {
            int m = 2 + rb * 32 + lane;
            if (m > 125) continue;
            int t = tbase + m - 2;
            if (t >= TI) continue;
            float s[5];
            #pragma unroll
            for (int d = 0; d < 5; d++) {
                int rm = m - 2 + d;
                int tr = tbase + rm - 2;
                float v = eb[rm * EPITCH + o] + bv;
                s[d] = (tr >= 2 && tr < TI - 2) ? v : 0.f;
            }
            float mean = (s[0] + s[1] + s[2] + s[3] + s[4]) * 0.2f;
            float den = fminf(fmaxf(s[2] - mean, 1.0f), BOUND);
            float y = fmaf(den, -0.70710678f, 1.6944272f);   // ~1/den on [1,1.415]
            y = y * (2.0f - den * y);
            y = y * (2.0f - den * y);
            bool cv = (t >= 2) && (t < TI - 2);
            float d1 = cv ? eb[m * EPITCH + 64 + o]  : 0.f;
            float d2 = cv ? eb[m * EPITCH + 128 + o] : 0.f;
            float r = 0.25f * (s[2] + (d1 + d2) * y + 2.0f * (d2 - d1) * y * y);
            op[2 * (size_t)t] = r;
        }
    }
}

extern "C" void kernel_launch(void* const* d_in, const int* in_sizes, int n_in,
                              void* d_out, int out_size)
{
    const float* x = (const float*)d_in[0];
    const float* w = (const float*)d_in[1];
    const float* b = (const float*)d_in[2];
    float* out = (float*)d_out;

    pack_w<<<256, 64>>>(w);

    static int smem_set = 0;
    if (!smem_set) {
        cudaFuncSetAttribute(pconv_mma, cudaFuncAttributeMaxDynamicSharedMemorySize, SMEMSZ);
        smem_set = 1;
    }
    dim3 grid(NT, 16, 4);
    pconv_mma<<<grid, 256, SMEMSZ>>>(x, b, out);
}

// round 5
// speedup vs baseline: 2.9775x; 1.1320x over previous
#include <cuda_runtime.h>
#include <cuda_bf16.h>
#include <cstdint>

// x:(8,256,16384) f32, w:(256,64,13) f32, b:(256) f32 -> out:(8,256,16384) f32
// M=5,N=2 -> U=3, GROUPS=4, DIL=2
#define TI      8192
#define TFULL   16384
#define TSTRIDE 124
#define NT      67
#define XR      132
#define XPW     40                 // x row pitch (words)
#define BPW     40                 // B row pitch (words)
#define BROWS   192
#define BCHUNK  (BROWS * BPW * 4)  // 30720 B per hi or lo block
#define BCH16   (BCHUNK / 16)
#define EPITCH  194
#define BOUND   1.41421356237309515f

// smem layout (bytes): x hi/lo, then two double-buffered B (hi+lo) slots
#define XH_OFF   0
#define XL_OFF   (XR * XPW * 4)            // 21120
#define B_OFF(s) ((2 * XR * XPW * 4) + (s) * 2 * BCHUNK)   // 42240 + s*61440
#define SMEMSZ   (2 * XR * XPW * 4 + 4 * BCHUNK)           // 165120 (epilogue 99328 overlays)

// Pre-swizzled packed weights: [g][tap][hi/lo] blocks of 192 rows x 40 words
__device__ uint4 g_wB[4 * 5 * 2 * BCH16];

__device__ __forceinline__ int swz(int r) { return (r & 3) ^ ((r >> 2) & 3); }

__device__ __forceinline__ uint32_t smem_u32(const void* p) {
    uint32_t a;
    asm("{ .reg .u64 t; cvta.to.shared.u64 t, %1; cvt.u32.u64 %0, t; }" : "=r"(a) : "l"(p));
    return a;
}
__device__ __forceinline__ uint2 lds64(uint32_t addr) {
    uint2 v;
    asm volatile("ld.shared.v2.b32 {%0,%1}, [%2];" : "=r"(v.x), "=r"(v.y) : "r"(addr));
    return v;
}
__device__ __forceinline__ void cp16(uint32_t dst, const void* src) {
    asm volatile("cp.async.cg.shared.global [%0], [%1], 16;" :: "r"(dst), "l"(src) : "memory");
}
#define CP_COMMIT() asm volatile("cp.async.commit_group;" ::: "memory")
#define CP_WAIT(n)  asm volatile("cp.async.wait_group %0;" :: "n"(n) : "memory")

__device__ __forceinline__ void mma16816(float* c, uint32_t a0, uint32_t a1,
                                         uint32_t a2, uint32_t a3,
                                         uint32_t b0, uint32_t b1) {
    asm volatile(
        "mma.sync.aligned.m16n8k16.row.col.f32.bf16.bf16.f32 "
        "{%0,%1,%2,%3}, {%4,%5,%6,%7}, {%8,%9}, {%0,%1,%2,%3};"
        : "+f"(c[0]), "+f"(c[1]), "+f"(c[2]), "+f"(c[3])
        : "r"(a0), "r"(a1), "r"(a2), "r"(a3), "r"(b0), "r"(b1));
}

// ---------------- weight prep: fused filters, bf16 hi/lo, swizzled image ----------------
//  t0:  wc[j] = w[3j]
//  d1:  [-w2, w2-w5, w5-w8, w8-w11, w11]
//  d2:  [-w1, w1-w4, w4-w7, w7-w10, w10]
__global__ void pack_w(const float* __restrict__ w) {
    int o = blockIdx.x;      // 0..255
    int c = threadIdx.x;     // 0..63
    int g = o >> 6, oo = o & 63;
    const float* ws = w + ((size_t)o * 64 + c) * 13;
    float f[3][5];
    #pragma unroll
    for (int j = 0; j < 5; j++) f[0][j] = ws[3 * j];
    f[1][0] = -ws[2];  f[1][1] = ws[2] - ws[5];  f[1][2] = ws[5] - ws[8];
    f[1][3] = ws[8] - ws[11];  f[1][4] = ws[11];
    f[2][0] = -ws[1];  f[2][1] = ws[1] - ws[4];  f[2][2] = ws[4] - ws[7];
    f[2][3] = ws[7] - ws[10];  f[2][4] = ws[10];

    int wl  = c >> 1;
    int q   = wl & 3, hi = (wl >> 2) & 1, cblk = wl >> 3;
    int sub = c & 1;
    char* base = (char*)g_wB;
    #pragma unroll
    for (int fi = 0; fi < 3; fi++) {
        int n = fi * 64 + oo;
        int pw = cblk * 8 + 2 * (q ^ swz(n)) + hi;
        size_t rowoff = (size_t)n * BPW * 4 + (size_t)pw * 4 + sub * 2;
        #pragma unroll
        for (int j = 0; j < 5; j++) {
            float v = f[fi][j];
            __nv_bfloat16 vh = __float2bfloat16(v);
            __nv_bfloat16 vl = __float2bfloat16(v - __bfloat162float(vh));
            size_t bh = ((size_t)(g * 5 + j) * 2 + 0) * BCHUNK;
            size_t bl = ((size_t)(g * 5 + j) * 2 + 1) * BCHUNK;
            *(__nv_bfloat16*)(base + bh + rowoff) = vh;
            *(__nv_bfloat16*)(base + bl + rowoff) = vl;
        }
    }
}

// ---------------- main kernel ----------------
__global__ void __launch_bounds__(256, 1) pconv_mma(
    const float* __restrict__ x, const float* __restrict__ bias, float* __restrict__ out)
{
    extern __shared__ char smem[];
    const uint32_t sb = smem_u32(smem);
    const int tid = threadIdx.x, lane = tid & 31, wid = tid >> 5;
    const int wm = wid & 3, wn = wid >> 2;
    const int q = lane & 3, ls = lane >> 2;
    const int tbase = blockIdx.x * TSTRIDE;
    const int batch = blockIdx.y >> 1, phase = blockIdx.y & 1;
    const int g = blockIdx.z;

    const uint4* wB = g_wB + (size_t)g * 5 * 2 * BCH16;

    // prologue: async-copy tap 0 B into slot 0 (overlaps with x staging below)
    {
        const char* src = (const char*)(wB);
        for (int idx = tid; idx < 2 * BCH16; idx += 256)
            cp16(sb + B_OFF(0) + idx * 16, src + idx * 16);
        CP_COMMIT();
    }

    // ---- stage x tile: rows p = tbase-4+m, bf16 hi/lo, swizzled pair layout ----
    {
        uint32_t* xhw = (uint32_t*)(smem + XH_OFF);
        uint32_t* xlw = (uint32_t*)(smem + XL_OFF);
        const float* xg = x + ((size_t)batch * 256 + (size_t)g * 64) * TFULL + phase;
        for (int idx = tid; idx < 32 * XR; idx += 256) {
            int i = idx / XR;            // channel pair 0..31
            int m = idx - i * XR;        // row 0..131
            int p = tbase - 4 + m;
            float v0 = 0.f, v1 = 0.f;
            if (p >= 0 && p < TI) {
                v0 = xg[(size_t)(2 * i) * TFULL + 2 * (size_t)p];
                v1 = xg[(size_t)(2 * i + 1) * TFULL + 2 * (size_t)p];
            }
            __nv_bfloat16 h0 = __float2bfloat16(v0);
            __nv_bfloat16 l0 = __float2bfloat16(v0 - __bfloat162float(h0));
            __nv_bfloat16 h1 = __float2bfloat16(v1);
            __nv_bfloat16 l1 = __float2bfloat16(v1 - __bfloat162float(h1));
            int iq = i & 3, ih = (i >> 2) & 1, icb = i >> 3;
            int pw = icb * 8 + 2 * (iq ^ swz(m)) + ih;
            int off = m * XPW + pw;
            xhw[off] = (uint32_t)__bfloat16_as_ushort(h0) | ((uint32_t)__bfloat16_as_ushort(h1) << 16);
            xlw[off] = (uint32_t)__bfloat16_as_ushort(l0) | ((uint32_t)__bfloat16_as_ushort(l1) << 16);
        }
    }

    float acc[2][12][4];
    #pragma unroll
    for (int mi = 0; mi < 2; mi++)
        #pragma unroll
        for (int ni = 0; ni < 12; ni++)
            #pragma unroll
            for (int k = 0; k < 4; k++) acc[mi][ni][k] = 0.f;

    for (int j = 0; j < 5; j++) {
        // prefetch tap j+1 into the other slot (that slot's reads finished at
        // the end of iteration j-1, guarded by the trailing __syncthreads)
        if (j < 4) {
            const char* src = (const char*)(wB + (size_t)(j + 1) * 2 * BCH16);
            uint32_t dst = sb + B_OFF((j + 1) & 1);
            for (int idx = tid; idx < 2 * BCH16; idx += 256)
                cp16(dst + idx * 16, src + idx * 16);
            CP_COMMIT();
            CP_WAIT(1);     // tap j's copy done (own thread)
        } else {
            CP_WAIT(0);
        }
        __syncthreads();     // all threads' tap-j data visible; x tile ready (j==0)

        const uint32_t bhb = sb + B_OFF(j & 1);
        const uint32_t blb = bhb + BCHUNK;

        #pragma unroll
        for (int cblk = 0; cblk < 4; cblk++) {
            // A fragments (hi/lo)
            uint2 ah[2][2], al[2][2];
            #pragma unroll
            for (int mi = 0; mi < 2; mi++) {
                int r0 = wm * 32 + mi * 16 + ls + j;
                #pragma unroll
                for (int ro = 0; ro < 2; ro++) {
                    int r = r0 + ro * 8;
                    uint32_t woff = (uint32_t)(r * XPW + cblk * 8 + 2 * (q ^ swz(r))) * 4;
                    ah[mi][ro] = lds64(sb + XH_OFF + woff);
                    al[mi][ro] = lds64(sb + XL_OFF + woff);
                }
            }
            // B fragments, all 12 n-tiles, hi and lo
            uint2 bh[12], bl[12];
            #pragma unroll
            for (int ni = 0; ni < 12; ni++) {
                int n = wn * 96 + ni * 8 + ls;
                uint32_t woff = (uint32_t)(n * BPW + cblk * 8 + 2 * (q ^ swz(n))) * 4;
                bh[ni] = lds64(bhb + woff);
                bl[ni] = lds64(blb + woff);
            }
            // product-major: 24-deep independent chains per product pass
            #pragma unroll
            for (int ni = 0; ni < 12; ni++) {
                mma16816(acc[0][ni], ah[0][0].x, ah[0][1].x, ah[0][0].y, ah[0][1].y, bh[ni].x, bh[ni].y);
                mma16816(acc[1][ni], ah[1][0].x, ah[1][1].x, ah[1][0].y, ah[1][1].y, bh[ni].x, bh[ni].y);
            }
            #pragma unroll
            for (int ni = 0; ni < 12; ni++) {
                mma16816(acc[0][ni], al[0][0].x, al[0][1].x, al[0][0].y, al[0][1].y, bh[ni].x, bh[ni].y);
                mma16816(acc[1][ni], al[1][0].x, al[1][1].x, al[1][0].y, al[1][1].y, bh[ni].x, bh[ni].y);
            }
            #pragma unroll
            for (int ni = 0; ni < 12; ni++) {
                mma16816(acc[0][ni], ah[0][0].x, ah[0][1].x, ah[0][0].y, ah[0][1].y, bl[ni].x, bl[ni].y);
                mma16816(acc[1][ni], ah[1][0].x, ah[1][1].x, ah[1][0].y, ah[1][1].y, bl[ni].x, bl[ni].y);
            }
        }
        __syncthreads();     // reads of slot (j&1) done before it is overwritten at j+2
    }

    // ---- epilogue: dump acc -> smem [128][194] f32 (overlays stage buffers) ----
    float* eb = (float*)smem;
    #pragma unroll
    for (int mi = 0; mi < 2; mi++) {
        int r0 = wm * 32 + mi * 16 + ls;
        #pragma unroll
        for (int ni = 0; ni < 12; ni++) {
            int col = wn * 96 + ni * 8 + q * 2;
            *(float2*)&eb[r0 * EPITCH + col]       = make_float2(acc[mi][ni][0], acc[mi][ni][1]);
            *(float2*)&eb[(r0 + 8) * EPITCH + col] = make_float2(acc[mi][ni][2], acc[mi][ni][3]);
        }
    }
    __syncthreads();

    // outputs: rows m = 2..125 (t = tbase + m - 2), 64 channels
    #pragma unroll 1
    for (int ko = 0; ko < 8; ko++) {
        int o = wid * 8 + ko;
        float bv = __ldg(&bias[g * 64 + o]);
        float* op = out + ((size_t)batch * 256 + (size_t)g * 64 + o) * TFULL + phase;
        #pragma unroll 1
        for (int rb = 0; rb < 4; rb++) {
            int m = 2 + rb * 32 + lane;
            if (m > 125) continue;
            int t = tbase + m - 2;
            if (t >= TI) continue;
            float s[5];
            #pragma unroll
            for (int d = 0; d < 5; d++) {
                int rm = m - 2 + d;
                int tr = tbase + rm - 2;
                float v = eb[rm * EPITCH + o] + bv;
                s[d] = (tr >= 2 && tr < TI - 2) ? v : 0.f;
            }
            float mean = (s[0] + s[1] + s[2] + s[3] + s[4]) * 0.2f;
            float den = fminf(fmaxf(s[2] - mean, 1.0f), BOUND);
            float y = fmaf(den, -0.70710678f, 1.6944272f);   // ~1/den on [1,1.415]
            y = y * (2.0f - den * y);
            y = y * (2.0f - den * y);
            bool cv = (t >= 2) && (t < TI - 2);
            float d1 = cv ? eb[m * EPITCH + 64 + o]  : 0.f;
            float d2 = cv ? eb[m * EPITCH + 128 + o] : 0.f;
            float r = 0.25f * (s[2] + (d1 + d2) * y + 2.0f * (d2 - d1) * y * y);
            op[2 * (size_t)t] = r;
        }
    }
}

extern "C" void kernel_launch(void* const* d_in, const int* in_sizes, int n_in,
                              void* d_out, int out_size)
{
    const float* x = (const float*)d_in[0];
    const float* w = (const float*)d_in[1];
    const float* b = (const float*)d_in[2];
    float* out = (float*)d_out;

    pack_w<<<256, 64>>>(w);

    static int smem_set = 0;
    if (!smem_set) {
        cudaFuncSetAttribute(pconv_mma, cudaFuncAttributeMaxDynamicSharedMemorySize, SMEMSZ);
        smem_set = 1;
    }
    dim3 grid(NT, 16, 4);
    pconv_mma<<<grid, 256, SMEMSZ>>>(x, b, out);
}

// round 6
// speedup vs baseline: 4.6622x; 1.5658x over previous
#include <cuda_runtime.h>
#include <cuda_fp16.h>
#include <cstdint>

// x:(8,256,16384) f32, w:(256,64,13) f32, b:(256) f32 -> out:(8,256,16384) f32
// M=5,N=2 -> U=3, GROUPS=4, DIL=2
#define TI      8192
#define TFULL   16384
#define TSTRIDE 124
#define NT      67
#define XR      132
#define XPW     40                 // x row pitch (words)
#define BPW     40                 // B row pitch (words)
#define BROWS   192
#define BCHUNK  (BROWS * BPW * 4)  // 30720 B per tap (fp16, pairs packed)
#define BCH16   (BCHUNK / 16)      // 1920 uint4 per tap
#define EPITCH  194
#define BOUND   1.41421356237309515f

// smem layout (bytes): x tile, then 5 resident B taps
#define X_OFF    0
#define B_OFF    (XR * XPW * 4)                 // 21120 (128B aligned)
#define SMEMSZ   (B_OFF + 5 * BCHUNK)           // 174720 ; epilogue 128x194 f32 = 99328 overlays

// Pre-swizzled packed weights: [g][tap] blocks of 192 rows x 40 words (fp16 pairs)
__device__ uint4 g_wB[4 * 5 * BCH16];

__device__ __forceinline__ int swz(int r) { return (r & 3) ^ ((r >> 2) & 3); }

__device__ __forceinline__ uint32_t smem_u32(const void* p) {
    uint32_t a;
    asm("{ .reg .u64 t; cvta.to.shared.u64 t, %1; cvt.u32.u64 %0, t; }" : "=r"(a) : "l"(p));
    return a;
}
__device__ __forceinline__ uint2 lds64(uint32_t addr) {
    uint2 v;
    asm volatile("ld.shared.v2.b32 {%0,%1}, [%2];" : "=r"(v.x), "=r"(v.y) : "r"(addr));
    return v;
}
__device__ __forceinline__ void cp16(uint32_t dst, const void* src) {
    asm volatile("cp.async.cg.shared.global [%0], [%1], 16;" :: "r"(dst), "l"(src) : "memory");
}
#define CP_COMMIT() asm volatile("cp.async.commit_group;" ::: "memory")
#define CP_WAIT0()  asm volatile("cp.async.wait_group 0;" ::: "memory")

__device__ __forceinline__ void mma16816(float* c, uint32_t a0, uint32_t a1,
                                         uint32_t a2, uint32_t a3,
                                         uint32_t b0, uint32_t b1) {
    asm volatile(
        "mma.sync.aligned.m16n8k16.row.col.f32.f16.f16.f32 "
        "{%0,%1,%2,%3}, {%4,%5,%6,%7}, {%8,%9}, {%0,%1,%2,%3};"
        : "+f"(c[0]), "+f"(c[1]), "+f"(c[2]), "+f"(c[3])
        : "r"(a0), "r"(a1), "r"(a2), "r"(a3), "r"(b0), "r"(b1));
}

// ---------------- weight prep: fused filters, fp16, swizzled image ----------------
//  t0:  wc[j] = w[3j]
//  d1:  [-w2, w2-w5, w5-w8, w8-w11, w11]
//  d2:  [-w1, w1-w4, w4-w7, w7-w10, w10]
__global__ void pack_w(const float* __restrict__ w) {
    int o = blockIdx.x;      // 0..255
    int c = threadIdx.x;     // 0..63
    int g = o >> 6, oo = o & 63;
    const float* ws = w + ((size_t)o * 64 + c) * 13;
    float f[3][5];
    #pragma unroll
    for (int j = 0; j < 5; j++) f[0][j] = ws[3 * j];
    f[1][0] = -ws[2];  f[1][1] = ws[2] - ws[5];  f[1][2] = ws[5] - ws[8];
    f[1][3] = ws[8] - ws[11];  f[1][4] = ws[11];
    f[2][0] = -ws[1];  f[2][1] = ws[1] - ws[4];  f[2][2] = ws[4] - ws[7];
    f[2][3] = ws[7] - ws[10];  f[2][4] = ws[10];

    int wl  = c >> 1;
    int q   = wl & 3, hi = (wl >> 2) & 1, cblk = wl >> 3;
    int sub = c & 1;
    char* base = (char*)g_wB;
    #pragma unroll
    for (int fi = 0; fi < 3; fi++) {
        int n = fi * 64 + oo;
        int pw = cblk * 8 + 2 * (q ^ swz(n)) + hi;
        size_t rowoff = (size_t)n * BPW * 4 + (size_t)pw * 4 + sub * 2;
        #pragma unroll
        for (int j = 0; j < 5; j++) {
            size_t blk = (size_t)(g * 5 + j) * BCHUNK;
            *(__half*)(base + blk + rowoff) = __float2half_rn(f[fi][j]);
        }
    }
}

// ---------------- main kernel ----------------
// grid (67, 16, 4), 256 threads. Warp (wm = wid&3, wn = wid>>2): rows wm*32..+31,
// cols wn*96..+95. Tile row m <-> t = tbase + m - 2; A[m,(j,c)] = xs[tbase+m-4+j][c].
__global__ void __launch_bounds__(256, 1) pconv_mma(
    const float* __restrict__ x, const float* __restrict__ bias, float* __restrict__ out)
{
    extern __shared__ char smem[];
    const uint32_t sb = smem_u32(smem);
    const int tid = threadIdx.x, lane = tid & 31, wid = tid >> 5;
    const int wm = wid & 3, wn = wid >> 2;
    const int q = lane & 3, ls = lane >> 2;
    const int tbase = blockIdx.x * TSTRIDE;
    const int batch = blockIdx.y >> 1, phase = blockIdx.y & 1;
    const int g = blockIdx.z;

    // prologue: async-copy ALL 5 taps of B (153.6 KB), overlapped with x staging
    {
        const char* src = (const char*)(g_wB + (size_t)g * 5 * BCH16);
        for (int idx = tid; idx < 5 * BCH16; idx += 256)
            cp16(sb + B_OFF + idx * 16, src + idx * 16);
        CP_COMMIT();
    }

    // ---- stage x tile: rows p = tbase-4+m, fp16, swizzled pair layout ----
    {
        uint32_t* xw = (uint32_t*)(smem + X_OFF);
        const float* xg = x + ((size_t)batch * 256 + (size_t)g * 64) * TFULL + phase;
        for (int idx = tid; idx < 32 * XR; idx += 256) {
            int i = idx / XR;            // channel pair 0..31
            int m = idx - i * XR;        // row 0..131
            int p = tbase - 4 + m;
            float v0 = 0.f, v1 = 0.f;
            if (p >= 0 && p < TI) {
                v0 = xg[(size_t)(2 * i) * TFULL + 2 * (size_t)p];
                v1 = xg[(size_t)(2 * i + 1) * TFULL + 2 * (size_t)p];
            }
            __half h0 = __float2half_rn(v0), h1 = __float2half_rn(v1);
            int iq = i & 3, ih = (i >> 2) & 1, icb = i >> 3;
            int pw = icb * 8 + 2 * (iq ^ swz(m)) + ih;
            xw[m * XPW + pw] = (uint32_t)__half_as_ushort(h0)
                             | ((uint32_t)__half_as_ushort(h1) << 16);
        }
    }

    float acc[2][12][4];
    #pragma unroll
    for (int mi = 0; mi < 2; mi++)
        #pragma unroll
        for (int ni = 0; ni < 12; ni++)
            #pragma unroll
            for (int k = 0; k < 4; k++) acc[mi][ni][k] = 0.f;

    CP_WAIT0();
    __syncthreads();     // x tile + all B taps visible

    // ---- sync-free mainloop: 5 taps x 4 cblk, 24 MMAs each ----
    #pragma unroll
    for (int j = 0; j < 5; j++) {
        const uint32_t bb = sb + B_OFF + j * BCHUNK;
        #pragma unroll
        for (int cblk = 0; cblk < 4; cblk++) {
            uint2 ah[2][2];
            #pragma unroll
            for (int mi = 0; mi < 2; mi++) {
                int r0 = wm * 32 + mi * 16 + ls + j;
                #pragma unroll
                for (int ro = 0; ro < 2; ro++) {
                    int r = r0 + ro * 8;
                    uint32_t woff = (uint32_t)(r * XPW + cblk * 8 + 2 * (q ^ swz(r))) * 4;
                    ah[mi][ro] = lds64(sb + X_OFF + woff);
                }
            }
            uint2 bh[12];
            #pragma unroll
            for (int ni = 0; ni < 12; ni++) {
                int n = wn * 96 + ni * 8 + ls;
                uint32_t woff = (uint32_t)(n * BPW + cblk * 8 + 2 * (q ^ swz(n))) * 4;
                bh[ni] = lds64(bb + woff);
            }
            #pragma unroll
            for (int ni = 0; ni < 12; ni++) {
                mma16816(acc[0][ni], ah[0][0].x, ah[0][1].x, ah[0][0].y, ah[0][1].y, bh[ni].x, bh[ni].y);
                mma16816(acc[1][ni], ah[1][0].x, ah[1][1].x, ah[1][0].y, ah[1][1].y, bh[ni].x, bh[ni].y);
            }
        }
    }

    // ---- epilogue: dump acc -> smem [128][194] f32 (overlays stage buffers) ----
    __syncthreads();
    float* eb = (float*)smem;
    #pragma unroll
    for (int mi = 0; mi < 2; mi++) {
        int r0 = wm * 32 + mi * 16 + ls;
        #pragma unroll
        for (int ni = 0; ni < 12; ni++) {
            int col = wn * 96 + ni * 8 + q * 2;
            *(float2*)&eb[r0 * EPITCH + col]       = make_float2(acc[mi][ni][0], acc[mi][ni][1]);
            *(float2*)&eb[(r0 + 8) * EPITCH + col] = make_float2(acc[mi][ni][2], acc[mi][ni][3]);
        }
    }
    __syncthreads();

    // outputs: rows m = 2..125 (t = tbase + m - 2), 64 channels
    #pragma unroll 1
    for (int ko = 0; ko < 8; ko++) {
        int o = wid * 8 + ko;
        float bv = __ldg(&bias[g * 64 + o]);
        float* op = out + ((size_t)batch * 256 + (size_t)g * 64 + o) * TFULL + phase;
        #pragma unroll 1
        for (int rb = 0; rb < 4; rb++) {
            int m = 2 + rb * 32 + lane;
            if (m > 125) continue;
            int t = tbase + m - 2;
            if (t >= TI) continue;
            float s[5];
            #pragma unroll
            for (int d = 0; d < 5; d++) {
                int rm = m - 2 + d;
                int tr = tbase + rm - 2;
                float v = eb[rm * EPITCH + o] + bv;
                s[d] = (tr >= 2 && tr < TI - 2) ? v : 0.f;
            }
            float mean = (s[0] + s[1] + s[2] + s[3] + s[4]) * 0.2f;
            float den = fminf(fmaxf(s[2] - mean, 1.0f), BOUND);
            float y = fmaf(den, -0.70710678f, 1.6944272f);   // ~1/den on [1,1.415]
            y = y * (2.0f - den * y);
            y = y * (2.0f - den * y);
            bool cv = (t >= 2) && (t < TI - 2);
            float d1 = cv ? eb[m * EPITCH + 64 + o]  : 0.f;
            float d2 = cv ? eb[m * EPITCH + 128 + o] : 0.f;
            float r = 0.25f * (s[2] + (d1 + d2) * y + 2.0f * (d2 - d1) * y * y);
            op[2 * (size_t)t] = r;
        }
    }
}

extern "C" void kernel_launch(void* const* d_in, const int* in_sizes, int n_in,
                              void* d_out, int out_size)
{
    const float* x = (const float*)d_in[0];
    const float* w = (const float*)d_in[1];
    const float* b = (const float*)d_in[2];
    float* out = (float*)d_out;

    pack_w<<<256, 64>>>(w);

    cudaFuncSetAttribute(pconv_mma, cudaFuncAttributeMaxDynamicSharedMemorySize, SMEMSZ);
    dim3 grid(NT, 16, 4);
    pconv_mma<<<grid, 256, SMEMSZ>>>(x, b, out);
}

// round 7
// speedup vs baseline: 4.6646x; 1.0005x over previous
#include <cuda_runtime.h>
#include <cuda_fp16.h>
#include <cstdint>

// x:(8,256,16384) f32, w:(256,64,13) f32, b:(256) f32 -> out:(8,256,16384) f32
// M=5,N=2 -> U=3, GROUPS=4, DIL=2
#define TI      8192
#define TFULL   16384
#define TSTRIDE 124
#define NT      67
#define XR      132
#define XPW     40                 // x row pitch (words)
#define BPW     40                 // B row pitch (words)
#define BROWS   192
#define BCHUNK  (BROWS * BPW * 4)  // 30720 B per tap (fp16, pairs packed)
#define BCH16   (BCHUNK / 16)      // 1920 uint4 per tap
#define EPITCH  194
#define BOUND   1.41421356237309515f

// smem layout (bytes): x tile, then 5 resident B taps
#define X_OFF    0
#define B_OFF    (XR * XPW * 4)                 // 21120 (128B aligned)
#define SMEMSZ   (B_OFF + 5 * BCHUNK)           // 174720 ; epilogue 128x194 f32 = 99328 overlays

// Pre-swizzled packed weights: [g][tap] blocks of 192 rows x 40 words (fp16 pairs)
__device__ uint4 g_wB[4 * 5 * BCH16];

__device__ __forceinline__ int swz(int r) { return (r & 3) ^ ((r >> 2) & 3); }

__device__ __forceinline__ uint32_t smem_u32(const void* p) {
    uint32_t a;
    asm("{ .reg .u64 t; cvta.to.shared.u64 t, %1; cvt.u32.u64 %0, t; }" : "=r"(a) : "l"(p));
    return a;
}
__device__ __forceinline__ uint2 lds64(uint32_t addr) {
    uint2 v;
    asm volatile("ld.shared.v2.b32 {%0,%1}, [%2];" : "=r"(v.x), "=r"(v.y) : "r"(addr));
    return v;
}
__device__ __forceinline__ void cp16(uint32_t dst, const void* src) {
    asm volatile("cp.async.cg.shared.global [%0], [%1], 16;" :: "r"(dst), "l"(src) : "memory");
}
#define CP_COMMIT() asm volatile("cp.async.commit_group;" ::: "memory")
#define CP_WAIT0()  asm volatile("cp.async.wait_group 0;" ::: "memory")

__device__ __forceinline__ void mma16816(float* c, uint32_t a0, uint32_t a1,
                                         uint32_t a2, uint32_t a3,
                                         uint32_t b0, uint32_t b1) {
    asm volatile(
        "mma.sync.aligned.m16n8k16.row.col.f32.f16.f16.f32 "
        "{%0,%1,%2,%3}, {%4,%5,%6,%7}, {%8,%9}, {%0,%1,%2,%3};"
        : "+f"(c[0]), "+f"(c[1]), "+f"(c[2]), "+f"(c[3])
        : "r"(a0), "r"(a1), "r"(a2), "r"(a3), "r"(b0), "r"(b1));
}

// ---------------- weight prep: fused filters, fp16, swizzled image ----------------
//  t0:  wc[j] = w[3j]
//  d1:  [-w2, w2-w5, w5-w8, w8-w11, w11]
//  d2:  [-w1, w1-w4, w4-w7, w7-w10, w10]
__global__ void pack_w(const float* __restrict__ w) {
    int o = blockIdx.x;      // 0..255
    int c = threadIdx.x;     // 0..63
    int g = o >> 6, oo = o & 63;
    const float* ws = w + ((size_t)o * 64 + c) * 13;
    float f[3][5];
    #pragma unroll
    for (int j = 0; j < 5; j++) f[0][j] = ws[3 * j];
    f[1][0] = -ws[2];  f[1][1] = ws[2] - ws[5];  f[1][2] = ws[5] - ws[8];
    f[1][3] = ws[8] - ws[11];  f[1][4] = ws[11];
    f[2][0] = -ws[1];  f[2][1] = ws[1] - ws[4];  f[2][2] = ws[4] - ws[7];
    f[2][3] = ws[7] - ws[10];  f[2][4] = ws[10];

    int wl  = c >> 1;
    int q   = wl & 3, hi = (wl >> 2) & 1, cblk = wl >> 3;
    int sub = c & 1;
    char* base = (char*)g_wB;
    #pragma unroll
    for (int fi = 0; fi < 3; fi++) {
        int n = fi * 64 + oo;
        int pw = cblk * 8 + 2 * (q ^ swz(n)) + hi;
        size_t rowoff = (size_t)n * BPW * 4 + (size_t)pw * 4 + sub * 2;
        #pragma unroll
        for (int j = 0; j < 5; j++) {
            size_t blk = (size_t)(g * 5 + j) * BCHUNK;
            *(__half*)(base + blk + rowoff) = __float2half_rn(f[fi][j]);
        }
    }
}

// ---------------- main kernel ----------------
// grid (67, 16, 4), 256 threads. Warp (wm = wid&3, wn = wid>>2): rows wm*32..+31,
// cols wn*96..+95. Tile row m <-> t = tbase + m - 2; A[m,(j,c)] = xs[tbase+m-4+j][c].
__global__ void __launch_bounds__(256, 1) pconv_mma(
    const float* __restrict__ x, const float* __restrict__ bias, float* __restrict__ out)
{
    extern __shared__ char smem[];
    const uint32_t sb = smem_u32(smem);
    const int tid = threadIdx.x, lane = tid & 31, wid = tid >> 5;
    const int wm = wid & 3, wn = wid >> 2;
    const int q = lane & 3, ls = lane >> 2;
    const int tbase = blockIdx.x * TSTRIDE;
    const int batch = blockIdx.y >> 1, phase = blockIdx.y & 1;
    const int g = blockIdx.z;

    // prologue: async-copy ALL 5 taps of B (153.6 KB), overlapped with x staging
    {
        const char* src = (const char*)(g_wB + (size_t)g * 5 * BCH16);
        for (int idx = tid; idx < 5 * BCH16; idx += 256)
            cp16(sb + B_OFF + idx * 16, src + idx * 16);
        CP_COMMIT();
    }

    // ---- stage x tile: rows p = tbase-4+m, fp16, swizzled pair layout ----
    {
        uint32_t* xw = (uint32_t*)(smem + X_OFF);
        const float* xg = x + ((size_t)batch * 256 + (size_t)g * 64) * TFULL + phase;
        for (int idx = tid; idx < 32 * XR; idx += 256) {
            int i = idx / XR;            // channel pair 0..31
            int m = idx - i * XR;        // row 0..131
            int p = tbase - 4 + m;
            float v0 = 0.f, v1 = 0.f;
            if (p >= 0 && p < TI) {
                v0 = xg[(size_t)(2 * i) * TFULL + 2 * (size_t)p];
                v1 = xg[(size_t)(2 * i + 1) * TFULL + 2 * (size_t)p];
            }
            __half h0 = __float2half_rn(v0), h1 = __float2half_rn(v1);
            int iq = i & 3, ih = (i >> 2) & 1, icb = i >> 3;
            int pw = icb * 8 + 2 * (iq ^ swz(m)) + ih;
            xw[m * XPW + pw] = (uint32_t)__half_as_ushort(h0)
                             | ((uint32_t)__half_as_ushort(h1) << 16);
        }
    }

    float acc[2][12][4];
    #pragma unroll
    for (int mi = 0; mi < 2; mi++)
        #pragma unroll
        for (int ni = 0; ni < 12; ni++)
            #pragma unroll
            for (int k = 0; k < 4; k++) acc[mi][ni][k] = 0.f;

    CP_WAIT0();
    __syncthreads();     // x tile + all B taps visible

    // ---- sync-free mainloop: 5 taps x 4 cblk, 24 MMAs each ----
    #pragma unroll
    for (int j = 0; j < 5; j++) {
        const uint32_t bb = sb + B_OFF + j * BCHUNK;
        #pragma unroll
        for (int cblk = 0; cblk < 4; cblk++) {
            uint2 ah[2][2];
            #pragma unroll
            for (int mi = 0; mi < 2; mi++) {
                int r0 = wm * 32 + mi * 16 + ls + j;
                #pragma unroll
                for (int ro = 0; ro < 2; ro++) {
                    int r = r0 + ro * 8;
                    uint32_t woff = (uint32_t)(r * XPW + cblk * 8 + 2 * (q ^ swz(r))) * 4;
                    ah[mi][ro] = lds64(sb + X_OFF + woff);
                }
            }
            uint2 bh[12];
            #pragma unroll
            for (int ni = 0; ni < 12; ni++) {
                int n = wn * 96 + ni * 8 + ls;
                uint32_t woff = (uint32_t)(n * BPW + cblk * 8 + 2 * (q ^ swz(n))) * 4;
                bh[ni] = lds64(bb + woff);
            }
            #pragma unroll
            for (int ni = 0; ni < 12; ni++) {
                mma16816(acc[0][ni], ah[0][0].x, ah[0][1].x, ah[0][0].y, ah[0][1].y, bh[ni].x, bh[ni].y);
                mma16816(acc[1][ni], ah[1][0].x, ah[1][1].x, ah[1][0].y, ah[1][1].y, bh[ni].x, bh[ni].y);
            }
        }
    }

    // ---- epilogue: dump acc -> smem [128][194] f32 (overlays stage buffers) ----
    __syncthreads();
    float* eb = (float*)smem;
    #pragma unroll
    for (int mi = 0; mi < 2; mi++) {
        int r0 = wm * 32 + mi * 16 + ls;
        #pragma unroll
        for (int ni = 0; ni < 12; ni++) {
            int col = wn * 96 + ni * 8 + q * 2;
            *(float2*)&eb[r0 * EPITCH + col]       = make_float2(acc[mi][ni][0], acc[mi][ni][1]);
            *(float2*)&eb[(r0 + 8) * EPITCH + col] = make_float2(acc[mi][ni][2], acc[mi][ni][3]);
        }
    }
    __syncthreads();

    // outputs: rows m = 2..125 (t = tbase + m - 2), 64 channels
    #pragma unroll 1
    for (int ko = 0; ko < 8; ko++) {
        int o = wid * 8 + ko;
        float bv = __ldg(&bias[g * 64 + o]);
        float* op = out + ((size_t)batch * 256 + (size_t)g * 64 + o) * TFULL + phase;
        #pragma unroll 1
        for (int rb = 0; rb < 4; rb++) {
            int m = 2 + rb * 32 + lane;
            if (m > 125) continue;
            int t = tbase + m - 2;
            if (t >= TI) continue;
            float s[5];
            #pragma unroll
            for (int d = 0; d < 5; d++) {
                int rm = m - 2 + d;
                int tr = tbase + rm - 2;
                float v = eb[rm * EPITCH + o] + bv;
                s[d] = (tr >= 2 && tr < TI - 2) ? v : 0.f;
            }
            float mean = (s[0] + s[1] + s[2] + s[3] + s[4]) * 0.2f;
            float den = fminf(fmaxf(s[2] - mean, 1.0f), BOUND);
            float y = fmaf(den, -0.70710678f, 1.6944272f);   // ~1/den on [1,1.415]
            y = y * (2.0f - den * y);
            y = y * (2.0f - den * y);
            bool cv = (t >= 2) && (t < TI - 2);
            float d1 = cv ? eb[m * EPITCH + 64 + o]  : 0.f;
            float d2 = cv ? eb[m * EPITCH + 128 + o] : 0.f;
            float r = 0.25f * (s[2] + (d1 + d2) * y + 2.0f * (d2 - d1) * y * y);
            op[2 * (size_t)t] = r;
        }
    }
}

extern "C" void kernel_launch(void* const* d_in, const int* in_sizes, int n_in,
                              void* d_out, int out_size)
{
    const float* x = (const float*)d_in[0];
    const float* w = (const float*)d_in[1];
    const float* b = (const float*)d_in[2];
    float* out = (float*)d_out;

    pack_w<<<256, 64>>>(w);

    cudaFuncSetAttribute(pconv_mma, cudaFuncAttributeMaxDynamicSharedMemorySize, SMEMSZ);
    dim3 grid(NT, 16, 4);
    pconv_mma<<<grid, 256, SMEMSZ>>>(x, b, out);
}

// round 8
// speedup vs baseline: 7.1035x; 1.5228x over previous
#include <cuda_runtime.h>
#include <cuda_fp16.h>
#include <cstdint>

// x:(8,256,16384) f32, w:(256,64,13) f32, b:(256) f32 -> out:(8,256,16384) f32
// M=5,N=2 -> U=3, GROUPS=4, DIL=2
#define TI      8192
#define TFULL   16384
#define TSTRIDE 60
#define NT      137                // ceil(8192/60)
#define XR      68
#define XPW     40                 // x row pitch (words)
#define BPW     40                 // B row pitch (words)
#define BROWS   192
#define BCHUNK  (BROWS * BPW * 4)  // 30720 B per tap (fp16 pairs)
#define BCH16   (BCHUNK / 16)      // 1920 uint4 per tap
#define EPITCH  194
#define BOUND   1.41421356237309515f

// smem layout (bytes): x tile, then 2 double-buffered B tap slots
#define X_OFF    0
#define B_OFF(s) ((XR * XPW * 4) + (s) * BCHUNK)   // 10880 + s*30720
#define SMEMSZ   (XR * XPW * 4 + 2 * BCHUNK)       // 72320 ; epilogue 64x194 f32 = 49664 overlays

// Pre-swizzled packed weights: [g][tap] blocks of 192 rows x 40 words (fp16 pairs)
__device__ uint4 g_wB[4 * 5 * BCH16];

__device__ __forceinline__ int swz(int r) { return (r & 3) ^ ((r >> 2) & 3); }

__device__ __forceinline__ uint32_t smem_u32(const void* p) {
    uint32_t a;
    asm("{ .reg .u64 t; cvta.to.shared.u64 t, %1; cvt.u32.u64 %0, t; }" : "=r"(a) : "l"(p));
    return a;
}
__device__ __forceinline__ uint2 lds64(uint32_t addr) {
    uint2 v;
    asm volatile("ld.shared.v2.b32 {%0,%1}, [%2];" : "=r"(v.x), "=r"(v.y) : "r"(addr));
    return v;
}
__device__ __forceinline__ void cp16(uint32_t dst, const void* src) {
    asm volatile("cp.async.cg.shared.global [%0], [%1], 16;" :: "r"(dst), "l"(src) : "memory");
}
#define CP_COMMIT() asm volatile("cp.async.commit_group;" ::: "memory")
#define CP_WAIT(n)  asm volatile("cp.async.wait_group %0;" :: "n"(n) : "memory")

__device__ __forceinline__ void mma16816(float* c, uint32_t a0, uint32_t a1,
                                         uint32_t a2, uint32_t a3,
                                         uint32_t b0, uint32_t b1) {
    asm volatile(
        "mma.sync.aligned.m16n8k16.row.col.f32.f16.f16.f32 "
        "{%0,%1,%2,%3}, {%4,%5,%6,%7}, {%8,%9}, {%0,%1,%2,%3};"
        : "+f"(c[0]), "+f"(c[1]), "+f"(c[2]), "+f"(c[3])
        : "r"(a0), "r"(a1), "r"(a2), "r"(a3), "r"(b0), "r"(b1));
}

// ---------------- weight prep: fused filters, fp16, swizzled image ----------------
//  t0:  wc[j] = w[3j]
//  d1:  [-w2, w2-w5, w5-w8, w8-w11, w11]
//  d2:  [-w1, w1-w4, w4-w7, w7-w10, w10]
__global__ void pack_w(const float* __restrict__ w) {
    int o = blockIdx.x;      // 0..255
    int c = threadIdx.x;     // 0..63
    int g = o >> 6, oo = o & 63;
    const float* ws = w + ((size_t)o * 64 + c) * 13;
    float f[3][5];
    #pragma unroll
    for (int j = 0; j < 5; j++) f[0][j] = ws[3 * j];
    f[1][0] = -ws[2];  f[1][1] = ws[2] - ws[5];  f[1][2] = ws[5] - ws[8];
    f[1][3] = ws[8] - ws[11];  f[1][4] = ws[11];
    f[2][0] = -ws[1];  f[2][1] = ws[1] - ws[4];  f[2][2] = ws[4] - ws[7];
    f[2][3] = ws[7] - ws[10];  f[2][4] = ws[10];

    int wl  = c >> 1;
    int q   = wl & 3, hi = (wl >> 2) & 1, cblk = wl >> 3;
    int sub = c & 1;
    char* base = (char*)g_wB;
    #pragma unroll
    for (int fi = 0; fi < 3; fi++) {
        int n = fi * 64 + oo;
        int pw = cblk * 8 + 2 * (q ^ swz(n)) + hi;
        size_t rowoff = (size_t)n * BPW * 4 + (size_t)pw * 4 + sub * 2;
        #pragma unroll
        for (int j = 0; j < 5; j++) {
            size_t blk = (size_t)(g * 5 + j) * BCHUNK;
            *(__half*)(base + blk + rowoff) = __float2half_rn(f[fi][j]);
        }
    }
}

// ---------------- main kernel ----------------
// grid (137, 16, 4), 256 threads, 3 CTAs/SM.
// Warp (wm = wid&1, wn = wid>>1): rows wm*32..+31 of 64, cols wn*48..+47 of 192.
// Tile row m <-> t = tbase + m - 2; A[m,(j,c)] = xs[tbase + m - 4 + j][c].
__global__ void __launch_bounds__(256, 3) pconv_mma(
    const float* __restrict__ x, const float* __restrict__ bias, float* __restrict__ out)
{
    extern __shared__ char smem[];
    const uint32_t sb = smem_u32(smem);
    const int tid = threadIdx.x, lane = tid & 31, wid = tid >> 5;
    const int wm = wid & 1, wn = wid >> 1;
    const int q = lane & 3, ls = lane >> 2;
    const int tbase = blockIdx.x * TSTRIDE;
    const int batch = blockIdx.y >> 1, phase = blockIdx.y & 1;
    const int g = blockIdx.z;

    const uint4* wB = g_wB + (size_t)g * 5 * BCH16;

    // prologue: async-copy tap 0 into slot 0 (overlaps x staging)
    {
        const char* src = (const char*)wB;
        for (int idx = tid; idx < BCH16; idx += 256)
            cp16(sb + B_OFF(0) + idx * 16, src + idx * 16);
        CP_COMMIT();
    }

    // ---- stage x tile: rows p = tbase-4+m, fp16, swizzled pair layout ----
    {
        uint32_t* xw = (uint32_t*)(smem + X_OFF);
        const float* xg = x + ((size_t)batch * 256 + (size_t)g * 64) * TFULL + phase;
        for (int idx = tid; idx < 32 * XR; idx += 256) {
            int i = idx / XR;            // channel pair 0..31
            int m = idx - i * XR;        // row 0..67
            int p = tbase - 4 + m;
            float v0 = 0.f, v1 = 0.f;
            if (p >= 0 && p < TI) {
                v0 = xg[(size_t)(2 * i) * TFULL + 2 * (size_t)p];
                v1 = xg[(size_t)(2 * i + 1) * TFULL + 2 * (size_t)p];
            }
            __half h0 = __float2half_rn(v0), h1 = __float2half_rn(v1);
            int iq = i & 3, ih = (i >> 2) & 1, icb = i >> 3;
            int pw = icb * 8 + 2 * (iq ^ swz(m)) + ih;
            xw[m * XPW + pw] = (uint32_t)__half_as_ushort(h0)
                             | ((uint32_t)__half_as_ushort(h1) << 16);
        }
    }

    float acc[2][6][4];
    #pragma unroll
    for (int mi = 0; mi < 2; mi++)
        #pragma unroll
        for (int ni = 0; ni < 6; ni++)
            #pragma unroll
            for (int k = 0; k < 4; k++) acc[mi][ni][k] = 0.f;

    for (int j = 0; j < 5; j++) {
        if (j < 4) {   // prefetch tap j+1 into the other slot
            const char* src = (const char*)(wB + (size_t)(j + 1) * BCH16);
            uint32_t dst = sb + B_OFF((j + 1) & 1);
            for (int idx = tid; idx < BCH16; idx += 256)
                cp16(dst + idx * 16, src + idx * 16);
            CP_COMMIT();
            CP_WAIT(1);
        } else {
            CP_WAIT(0);
        }
        __syncthreads();   // tap j visible to all; x tile ready (j==0)

        const uint32_t bb = sb + B_OFF(j & 1);
        #pragma unroll
        for (int cblk = 0; cblk < 4; cblk++) {
            uint2 ah[2][2];
            #pragma unroll
            for (int mi = 0; mi < 2; mi++) {
                int r0 = wm * 32 + mi * 16 + ls + j;
                #pragma unroll
                for (int ro = 0; ro < 2; ro++) {
                    int r = r0 + ro * 8;
                    uint32_t woff = (uint32_t)(r * XPW + cblk * 8 + 2 * (q ^ swz(r))) * 4;
                    ah[mi][ro] = lds64(sb + X_OFF + woff);
                }
            }
            uint2 bh[6];
            #pragma unroll
            for (int ni = 0; ni < 6; ni++) {
                int n = wn * 48 + ni * 8 + ls;
                uint32_t woff = (uint32_t)(n * BPW + cblk * 8 + 2 * (q ^ swz(n))) * 4;
                bh[ni] = lds64(bb + woff);
            }
            #pragma unroll
            for (int ni = 0; ni < 6; ni++) {
                mma16816(acc[0][ni], ah[0][0].x, ah[0][1].x, ah[0][0].y, ah[0][1].y, bh[ni].x, bh[ni].y);
                mma16816(acc[1][ni], ah[1][0].x, ah[1][1].x, ah[1][0].y, ah[1][1].y, bh[ni].x, bh[ni].y);
            }
        }
        __syncthreads();   // slot (j&1) reads done before overwrite at j+2
    }

    // ---- epilogue: dump acc -> smem [64][194] f32 (overlays stage buffers) ----
    float* eb = (float*)smem;
    #pragma unroll
    for (int mi = 0; mi < 2; mi++) {
        int r0 = wm * 32 + mi * 16 + ls;
        #pragma unroll
        for (int ni = 0; ni < 6; ni++) {
            int col = wn * 48 + ni * 8 + q * 2;
            *(float2*)&eb[r0 * EPITCH + col]       = make_float2(acc[mi][ni][0], acc[mi][ni][1]);
            *(float2*)&eb[(r0 + 8) * EPITCH + col] = make_float2(acc[mi][ni][2], acc[mi][ni][3]);
        }
    }
    __syncthreads();

    // outputs: rows m = 2..61 (t = tbase + m - 2), 64 channels
    #pragma unroll 1
    for (int ko = 0; ko < 8; ko++) {
        int o = wid * 8 + ko;
        float bv = __ldg(&bias[g * 64 + o]);
        float* op = out + ((size_t)batch * 256 + (size_t)g * 64 + o) * TFULL + phase;
        #pragma unroll 1
        for (int rb = 0; rb < 2; rb++) {
            int m = 2 + rb * 32 + lane;
            if (m > 61) continue;
            int t = tbase + m - 2;
            if (t >= TI) continue;
            float s[5];
            #pragma unroll
            for (int d = 0; d < 5; d++) {
                int rm = m - 2 + d;
                int tr = tbase + rm - 2;
                float v = eb[rm * EPITCH + o] + bv;
                s[d] = (tr >= 2 && tr < TI - 2) ? v : 0.f;
            }
            float mean = (s[0] + s[1] + s[2] + s[3] + s[4]) * 0.2f;
            float den = fminf(fmaxf(s[2] - mean, 1.0f), BOUND);
            float y = fmaf(den, -0.70710678f, 1.6944272f);   // ~1/den on [1,1.415]
            y = y * (2.0f - den * y);
            y = y * (2.0f - den * y);
            bool cv = (t >= 2) && (t < TI - 2);
            float d1 = cv ? eb[m * EPITCH + 64 + o]  : 0.f;
            float d2 = cv ? eb[m * EPITCH + 128 + o] : 0.f;
            float r = 0.25f * (s[2] + (d1 + d2) * y + 2.0f * (d2 - d1) * y * y);
            op[2 * (size_t)t] = r;
        }
    }
}

extern "C" void kernel_launch(void* const* d_in, const int* in_sizes, int n_in,
                              void* d_out, int out_size)
{
    const float* x = (const float*)d_in[0];
    const float* w = (const float*)d_in[1];
    const float* b = (const float*)d_in[2];
    float* out = (float*)d_out;

    pack_w<<<256, 64>>>(w);

    cudaFuncSetAttribute(pconv_mma, cudaFuncAttributeMaxDynamicSharedMemorySize, SMEMSZ);
    dim3 grid(NT, 16, 4);
    pconv_mma<<<grid, 256, SMEMSZ>>>(x, b, out);
}

// round 9
// speedup vs baseline: 8.6239x; 1.2140x over previous
#include <cuda_runtime.h>
#include <cuda_fp16.h>
#include <cstdint>

// x:(8,256,16384) f32, w:(256,64,13) f32, b:(256) f32 -> out:(8,256,16384) f32
// M=5,N=2 -> U=3, GROUPS=4, DIL=2
#define TI      8192
#define TFULL   16384
#define TSTRIDE 60
#define NT      137                // ceil(8192/60)
#define XR      68
#define XPW     40                 // x row pitch (words)
#define BPW     40                 // B row pitch (words)
#define BROWS   192
#define BCHUNK  (BROWS * BPW * 4)  // 30720 B per tap (fp16 pairs)
#define BCH16   (BCHUNK / 16)      // 1920 uint4 per tap
#define EPITCH  195                // odd*? stride mod 32 = 3 -> conflict-free epilogue
#define BOUND   1.41421356237309515f

// smem layout (bytes): x tile, then 2 double-buffered B tap slots
#define X_OFF    0
#define B_OFF(s) ((XR * XPW * 4) + (s) * BCHUNK)   // 10880 + s*30720
#define SMEMSZ   (XR * XPW * 4 + 2 * BCHUNK)       // 72320 ; epilogue 64x195 f32 = 49920 overlays

// Pre-swizzled packed weights: [g][tap] blocks of 192 rows x 40 words (fp16 pairs)
__device__ uint4 g_wB[4 * 5 * BCH16];

__device__ __forceinline__ int swz(int r) { return (r & 3) ^ ((r >> 2) & 3); }

__device__ __forceinline__ uint32_t smem_u32(const void* p) {
    uint32_t a;
    asm("{ .reg .u64 t; cvta.to.shared.u64 t, %1; cvt.u32.u64 %0, t; }" : "=r"(a) : "l"(p));
    return a;
}
__device__ __forceinline__ uint2 lds64(uint32_t addr) {
    uint2 v;
    asm volatile("ld.shared.v2.b32 {%0,%1}, [%2];" : "=r"(v.x), "=r"(v.y) : "r"(addr));
    return v;
}
__device__ __forceinline__ void cp16(uint32_t dst, const void* src) {
    asm volatile("cp.async.cg.shared.global [%0], [%1], 16;" :: "r"(dst), "l"(src) : "memory");
}
#define CP_COMMIT() asm volatile("cp.async.commit_group;" ::: "memory")
#define CP_WAIT(n)  asm volatile("cp.async.wait_group %0;" :: "n"(n) : "memory")

__device__ __forceinline__ void mma16816(float* c, uint32_t a0, uint32_t a1,
                                         uint32_t a2, uint32_t a3,
                                         uint32_t b0, uint32_t b1) {
    asm volatile(
        "mma.sync.aligned.m16n8k16.row.col.f32.f16.f16.f32 "
        "{%0,%1,%2,%3}, {%4,%5,%6,%7}, {%8,%9}, {%0,%1,%2,%3};"
        : "+f"(c[0]), "+f"(c[1]), "+f"(c[2]), "+f"(c[3])
        : "r"(a0), "r"(a1), "r"(a2), "r"(a3), "r"(b0), "r"(b1));
}

// ---------------- weight prep: fused filters, fp16, swizzled image ----------------
//  t0:  wc[j] = w[3j]
//  d1:  [-w2, w2-w5, w5-w8, w8-w11, w11]
//  d2:  [-w1, w1-w4, w4-w7, w7-w10, w10]
__global__ void pack_w(const float* __restrict__ w) {
    int o = blockIdx.x;      // 0..255
    int c = threadIdx.x;     // 0..63
    int g = o >> 6, oo = o & 63;
    const float* ws = w + ((size_t)o * 64 + c) * 13;
    float f[3][5];
    #pragma unroll
    for (int j = 0; j < 5; j++) f[0][j] = ws[3 * j];
    f[1][0] = -ws[2];  f[1][1] = ws[2] - ws[5];  f[1][2] = ws[5] - ws[8];
    f[1][3] = ws[8] - ws[11];  f[1][4] = ws[11];
    f[2][0] = -ws[1];  f[2][1] = ws[1] - ws[4];  f[2][2] = ws[4] - ws[7];
    f[2][3] = ws[7] - ws[10];  f[2][4] = ws[10];

    int wl  = c >> 1;
    int q   = wl & 3, hi = (wl >> 2) & 1, cblk = wl >> 3;
    int sub = c & 1;
    char* base = (char*)g_wB;
    #pragma unroll
    for (int fi = 0; fi < 3; fi++) {
        int n = fi * 64 + oo;
        int pw = cblk * 8 + 2 * (q ^ swz(n)) + hi;
        size_t rowoff = (size_t)n * BPW * 4 + (size_t)pw * 4 + sub * 2;
        #pragma unroll
        for (int j = 0; j < 5; j++) {
            size_t blk = (size_t)(g * 5 + j) * BCHUNK;
            *(__half*)(base + blk + rowoff) = __float2half_rn(f[fi][j]);
        }
    }
}

// ---------------- main kernel ----------------
// grid (137, 16, 4), 256 threads, 3 CTAs/SM.
// Warp (wm = wid&1, wn = wid>>1): rows wm*32..+31 of 64, cols wn*48..+47 of 192.
// Tile row m <-> t = tbase + m - 2; A[m,(j,c)] = xs[tbase + m - 4 + j][c].
__global__ void __launch_bounds__(256, 3) pconv_mma(
    const float* __restrict__ x, const float* __restrict__ bias, float* __restrict__ out)
{
    extern __shared__ char smem[];
    const uint32_t sb = smem_u32(smem);
    const int tid = threadIdx.x, lane = tid & 31, wid = tid >> 5;
    const int wm = wid & 1, wn = wid >> 1;
    const int q = lane & 3, ls = lane >> 2;
    const int tbase = blockIdx.x * TSTRIDE;
    const int batch = blockIdx.y >> 1, phase = blockIdx.y & 1;
    const int g = blockIdx.z;

    const uint4* wB = g_wB + (size_t)g * 5 * BCH16;

    // prologue: async-copy tap 0 into slot 0 (overlaps x staging)
    {
        const char* src = (const char*)wB;
        for (int idx = tid; idx < BCH16; idx += 256)
            cp16(sb + B_OFF(0) + idx * 16, src + idx * 16);
        CP_COMMIT();
    }

    // ---- stage x tile: rows p = tbase-4+m, fp16, swizzled pair layout ----
    // division-free: lanes walk m (coalesced gmem), outer loops walk (i, mblk)
    {
        uint32_t* xw = (uint32_t*)(smem + X_OFF);
        const float* xg = x + ((size_t)batch * 256 + (size_t)g * 64) * TFULL + phase;
        const int i0 = wid;          // channel-pair base 0..7
        const int ml = lane;         // row within 32-block
        #pragma unroll
        for (int ib = 0; ib < 4; ib++) {
            int i = i0 + ib * 8;     // channel pair 0..31
            int iq = i & 3, ih = (i >> 2) & 1, icb = i >> 3;
            const float* xr0 = xg + (size_t)(2 * i) * TFULL;
            const float* xr1 = xg + (size_t)(2 * i + 1) * TFULL;
            #pragma unroll
            for (int mb = 0; mb < 3; mb++) {
                int m = ml + mb * 32;
                if (m >= XR) break;
                int p = tbase - 4 + m;
                float v0 = 0.f, v1 = 0.f;
                if (p >= 0 && p < TI) {
                    v0 = xr0[2 * (size_t)p];
                    v1 = xr1[2 * (size_t)p];
                }
                __half h0 = __float2half_rn(v0), h1 = __float2half_rn(v1);
                int pw = icb * 8 + 2 * (iq ^ swz(m)) + ih;
                xw[m * XPW + pw] = (uint32_t)__half_as_ushort(h0)
                                 | ((uint32_t)__half_as_ushort(h1) << 16);
            }
        }
    }

    float acc[2][6][4];
    #pragma unroll
    for (int mi = 0; mi < 2; mi++)
        #pragma unroll
        for (int ni = 0; ni < 6; ni++)
            #pragma unroll
            for (int k = 0; k < 4; k++) acc[mi][ni][k] = 0.f;

    // B fragment offsets are tap-invariant: precompute once
    uint32_t bofs[6];
    #pragma unroll
    for (int ni = 0; ni < 6; ni++) {
        int n = wn * 48 + ni * 8 + ls;
        bofs[ni] = (uint32_t)(n * BPW + 2 * (q ^ swz(n))) * 4;
    }

    #pragma unroll
    for (int j = 0; j < 5; j++) {
        if (j < 4) {   // prefetch tap j+1 into the other slot
            const char* src = (const char*)(wB + (size_t)(j + 1) * BCH16);
            uint32_t dst = sb + B_OFF((j + 1) & 1);
            for (int idx = tid; idx < BCH16; idx += 256)
                cp16(dst + idx * 16, src + idx * 16);
            CP_COMMIT();
            CP_WAIT(1);
        } else {
            CP_WAIT(0);
        }
        __syncthreads();   // tap j visible to all; x tile ready (j==0)

        const uint32_t bb = sb + B_OFF(j & 1);
        #pragma unroll
        for (int cblk = 0; cblk < 4; cblk++) {
            uint2 ah[2][2];
            #pragma unroll
            for (int mi = 0; mi < 2; mi++) {
                int r0 = wm * 32 + mi * 16 + ls + j;
                #pragma unroll
                for (int ro = 0; ro < 2; ro++) {
                    int r = r0 + ro * 8;
                    uint32_t woff = (uint32_t)(r * XPW + cblk * 8 + 2 * (q ^ swz(r))) * 4;
                    ah[mi][ro] = lds64(sb + X_OFF + woff);
                }
            }
            uint2 bh[6];
            #pragma unroll
            for (int ni = 0; ni < 6; ni++)
                bh[ni] = lds64(bb + bofs[ni] + cblk * 32);
            #pragma unroll
            for (int ni = 0; ni < 6; ni++) {
                mma16816(acc[0][ni], ah[0][0].x, ah[0][1].x, ah[0][0].y, ah[0][1].y, bh[ni].x, bh[ni].y);
                mma16816(acc[1][ni], ah[1][0].x, ah[1][1].x, ah[1][0].y, ah[1][1].y, bh[ni].x, bh[ni].y);
            }
        }
        __syncthreads();   // slot (j&1) reads done before overwrite at j+2
    }

    // ---- epilogue: dump acc -> smem [64][195] f32 (overlays stage buffers) ----
    float* eb = (float*)smem;
    #pragma unroll
    for (int mi = 0; mi < 2; mi++) {
        int r0 = wm * 32 + mi * 16 + ls;
        #pragma unroll
        for (int ni = 0; ni < 6; ni++) {
            int col = wn * 48 + ni * 8 + q * 2;
            eb[r0 * EPITCH + col]           = acc[mi][ni][0];
            eb[r0 * EPITCH + col + 1]       = acc[mi][ni][1];
            eb[(r0 + 8) * EPITCH + col]     = acc[mi][ni][2];
            eb[(r0 + 8) * EPITCH + col + 1] = acc[mi][ni][3];
        }
    }
    __syncthreads();

    const bool interior = (blockIdx.x > 0) && (blockIdx.x < NT - 1);
    float* outg = out + ((size_t)batch * 256 + (size_t)g * 64) * TFULL + phase;

    if (interior) {
        // fast path: every row/t valid, no masking
        #pragma unroll 1
        for (int ko = 0; ko < 8; ko++) {
            int o = wid * 8 + ko;
            float bv = __ldg(&bias[g * 64 + o]);
            float* op = outg + (size_t)o * TFULL;
            #pragma unroll
            for (int rb = 0; rb < 2; rb++) {
                int m = 2 + rb * 32 + lane;
                if (m > 61) continue;
                int t = tbase + m - 2;
                float s0 = eb[(m - 2) * EPITCH + o] + bv;
                float s1 = eb[(m - 1) * EPITCH + o] + bv;
                float s2 = eb[m * EPITCH + o] + bv;
                float s3 = eb[(m + 1) * EPITCH + o] + bv;
                float s4 = eb[(m + 2) * EPITCH + o] + bv;
                float mean = (s0 + s1 + s2 + s3 + s4) * 0.2f;
                float den = fminf(fmaxf(s2 - mean, 1.0f), BOUND);
                float y = fmaf(den, -0.70710678f, 1.6944272f);
                y = y * (2.0f - den * y);
                y = y * (2.0f - den * y);
                float d1 = eb[m * EPITCH + 64 + o];
                float d2 = eb[m * EPITCH + 128 + o];
                float r = 0.25f * (s2 + (d1 + d2) * y + 2.0f * (d2 - d1) * y * y);
                op[2 * (size_t)t] = r;
            }
        }
    } else {
        // edge path: masked (tiles 0 and NT-1 only)
        #pragma unroll 1
        for (int ko = 0; ko < 8; ko++) {
            int o = wid * 8 + ko;
            float bv = __ldg(&bias[g * 64 + o]);
            float* op = outg + (size_t)o * TFULL;
            #pragma unroll 1
            for (int rb = 0; rb < 2; rb++) {
                int m = 2 + rb * 32 + lane;
                if (m > 61) continue;
                int t = tbase + m - 2;
                if (t >= TI) continue;
                float s[5];
                #pragma unroll
                for (int d = 0; d < 5; d++) {
                    int rm = m - 2 + d;
                    int tr = tbase + rm - 2;
                    float v = eb[rm * EPITCH + o] + bv;
                    s[d] = (tr >= 2 && tr < TI - 2) ? v : 0.f;
                }
                float mean = (s[0] + s[1] + s[2] + s[3] + s[4]) * 0.2f;
                float den = fminf(fmaxf(s[2] - mean, 1.0f), BOUND);
                float y = fmaf(den, -0.70710678f, 1.6944272f);
                y = y * (2.0f - den * y);
                y = y * (2.0f - den * y);
                bool cv = (t >= 2) && (t < TI - 2);
                float d1 = cv ? eb[m * EPITCH + 64 + o]  : 0.f;
                float d2 = cv ? eb[m * EPITCH + 128 + o] : 0.f;
                float r = 0.25f * (s[2] + (d1 + d2) * y + 2.0f * (d2 - d1) * y * y);
                op[2 * (size_t)t] = r;
            }
        }
    }
}

extern "C" void kernel_launch(void* const* d_in, const int* in_sizes, int n_in,
                              void* d_out, int out_size)
{
    const float* x = (const float*)d_in[0];
    const float* w = (const float*)d_in[1];
    const float* b = (const float*)d_in[2];
    float* out = (float*)d_out;

    pack_w<<<256, 64>>>(w);

    cudaFuncSetAttribute(pconv_mma, cudaFuncAttributeMaxDynamicSharedMemorySize, SMEMSZ);
    dim3 grid(NT, 16, 4);
    pconv_mma<<<grid, 256, SMEMSZ>>>(x, b, out);
}